// round 12
// baseline (speedup 1.0000x reference)
#include <cuda_runtime.h>

#define N 8192
#define THREADS 256
#define ROWS_PER_BLOCK 8
#define KCHUNK 2048
#define NCHUNK (N / KCHUNK)                 // 4
#define ROWGROUPS (N / ROWS_PER_BLOCK)      // 1024
#define GRID (ROWGROUPS * NCHUNK)           // 4096
#define ITERS (KCHUNK / (32 * 4))           // 16 float4 iters per lane
#define ARRIVALS ((NCHUNK - 1) * ROWS_PER_BLOCK)   // 24 warp-arrivals (chunks 0..2)

__device__ float g_part[(NCHUNK - 1) * N];
__device__ unsigned int g_cnt[ROWGROUPS];   // zero-init; reset to 0 by finalizer block

__device__ __forceinline__ float fast_tanh(float v)
{
    float o;
    asm("tanh.approx.f32 %0, %1;" : "=f"(o) : "f"(v));
    return o;
}

__device__ __forceinline__ void red_release_add(unsigned int* p, unsigned int v)
{
    asm volatile("red.release.gpu.global.add.u32 [%0], %1;"
                 :: "l"(p), "r"(v) : "memory");
}

__device__ __forceinline__ unsigned int ld_acquire(const unsigned int* p)
{
    unsigned int v;
    asm volatile("ld.acquire.gpu.global.u32 %0, [%1];"
                 : "=r"(v) : "l"(p) : "memory");
    return v;
}

__device__ __forceinline__ float ld_acquire_f(const float* p)
{
    float v;
    asm volatile("ld.acquire.gpu.global.f32 %0, [%1];"
                 : "=f"(v) : "l"(p) : "memory");
    return v;
}

__global__ __launch_bounds__(THREADS) void gemv_fused_kernel(
    const float* __restrict__ x,
    const float* __restrict__ y,
    const float* __restrict__ W,
    float* __restrict__ out)
{
    __shared__ float r_s[KCHUNK];  // 8 KB

    const int tid   = threadIdx.x;
    const int bx    = blockIdx.x;
    const int chunk = bx >> 10;          // bx / ROWGROUPS (chunk-major)
    const int rowg  = bx & (ROWGROUPS - 1);
    const int col0  = chunk * KCHUNK;

    // Stage r-chunk with single-instruction MUFU tanh.
    {
        const float4* ysrc = reinterpret_cast<const float4*>(y + col0);
        float4* rdst = reinterpret_cast<float4*>(r_s);
        #pragma unroll
        for (int i = tid; i < KCHUNK / 4; i += THREADS) {
            float4 v = ysrc[i];
            float4 t;
            t.x = fast_tanh(v.x); t.y = fast_tanh(v.y);
            t.z = fast_tanh(v.z); t.w = fast_tanh(v.w);
            rdst[i] = t;
        }
    }
    __syncthreads();

    const int warp = tid >> 5;
    const int lane = tid & 31;
    const int row  = rowg * ROWS_PER_BLOCK + warp;

    const float4* __restrict__ Wrow =
        reinterpret_cast<const float4*>(W + (size_t)row * N + col0);
    const float4* rs4 = reinterpret_cast<const float4*>(r_s);

    float a0 = 0.f, a1 = 0.f, a2 = 0.f, a3 = 0.f;
    #pragma unroll
    for (int i = 0; i < ITERS; i += 4) {
        float4 w0 = Wrow[(i + 0) * 32 + lane];
        float4 w1 = Wrow[(i + 1) * 32 + lane];
        float4 w2 = Wrow[(i + 2) * 32 + lane];
        float4 w3 = Wrow[(i + 3) * 32 + lane];
        float4 v0 = rs4[(i + 0) * 32 + lane];
        float4 v1 = rs4[(i + 1) * 32 + lane];
        float4 v2 = rs4[(i + 2) * 32 + lane];
        float4 v3 = rs4[(i + 3) * 32 + lane];
        a0 += w0.x * v0.x + w0.y * v0.y + w0.z * v0.z + w0.w * v0.w;
        a1 += w1.x * v1.x + w1.y * v1.y + w1.z * v1.z + w1.w * v1.w;
        a2 += w2.x * v2.x + w2.y * v2.y + w2.z * v2.z + w2.w * v2.w;
        a3 += w3.x * v3.x + w3.y * v3.y + w3.z * v3.z + w3.w * v3.w;
    }
    float acc = (a0 + a1) + (a2 + a3);

    #pragma unroll
    for (int off = 16; off > 0; off >>= 1)
        acc += __shfl_xor_sync(0xFFFFFFFFu, acc, off);

    if (chunk < NCHUNK - 1) {
        // Producer chunks: publish partial + release arrival. No waiting;
        // warps retire independently (R8 retirement behavior preserved).
        if (lane == 0) {
            __stcg(&g_part[chunk * N + row], acc);
            red_release_add(&g_cnt[rowg], 1u);
        }
        return;
    }

    // Chunk 3 (launched last): finalize this rowgroup's 8 outputs.
    if (lane == 0) {
        // Expect ~zero spin: chunks 0..2 were launched (and finished) earlier.
        while (ld_acquire(&g_cnt[rowg]) != ARRIVALS)
            __nanosleep(32);
        float p0 = ld_acquire_f(&g_part[0 * N + row]);
        float p1 = ld_acquire_f(&g_part[1 * N + row]);
        float p2 = ld_acquire_f(&g_part[2 * N + row]);
        float sum = ((p0 + p1) + p2) + acc;   // fixed order -> deterministic
        const float DT  = 1e-3f;
        const float TAU = 1e-2f;
        float yr = y[row];
        out[row] = yr + DT * ((-yr + sum + x[row]) / TAU);
    }

    // All 8 warps of this block have observed cnt==ARRIVALS; reset for the
    // next graph replay (kernel boundary orders this vs. next launch).
    __syncthreads();
    if (tid == 0)
        g_cnt[rowg] = 0u;
}

extern "C" void kernel_launch(void* const* d_in, const int* in_sizes, int n_in,
                              void* d_out, int out_size)
{
    const float* x = (const float*)d_in[0];
    const float* y = (const float*)d_in[1];
    const float* W = (const float*)d_in[2];
    float* out = (float*)d_out;

    gemv_fused_kernel<<<GRID, THREADS>>>(x, y, W, out);
}

// round 13
// speedup vs baseline: 1.0019x; 1.0019x over previous
#include <cuda_runtime.h>
#include <cstdint>

#define N 8192
#define THREADS 256
#define ROWS_PER_BLOCK 8
#define GRID (N / ROWS_PER_BLOCK)   // 1024
#define DEPTH 4
#define STAGE_BYTES (N * 4)         // one full row = 32 KB

struct __align__(16) Smem {
    float w[DEPTH][N];                    // 4 x 32 KB ring
    float r[N];                           // 32 KB tanh(y)
    float warp_part[ROWS_PER_BLOCK][8];   // per-stage per-warp partials
    unsigned long long mbar[DEPTH];
};

__device__ __forceinline__ float fast_tanh(float v)
{
    float o;
    asm("tanh.approx.f32 %0, %1;" : "=f"(o) : "f"(v));
    return o;
}

__device__ __forceinline__ void mbar_init(uint32_t mbar, uint32_t count)
{
    asm volatile("mbarrier.init.shared.b64 [%0], %1;" :: "r"(mbar), "r"(count) : "memory");
}

__device__ __forceinline__ void mbar_expect_tx(uint32_t mbar, uint32_t bytes)
{
    asm volatile("mbarrier.arrive.expect_tx.shared.b64 _, [%0], %1;"
                 :: "r"(mbar), "r"(bytes) : "memory");
}

__device__ __forceinline__ void bulk_load(uint32_t dst_smem, const void* src, uint32_t bytes,
                                          uint32_t mbar)
{
    asm volatile("cp.async.bulk.shared::cta.global.mbarrier::complete_tx::bytes "
                 "[%0], [%1], %2, [%3];"
                 :: "r"(dst_smem), "l"(src), "r"(bytes), "r"(mbar) : "memory");
}

__device__ __forceinline__ void mbar_wait(uint32_t mbar, uint32_t parity)
{
    asm volatile(
        "{\n\t"
        ".reg .pred P;\n\t"
        "WAIT_%=:\n\t"
        "mbarrier.try_wait.parity.acquire.cta.shared::cta.b64 P, [%0], %1, 0x989680;\n\t"
        "@P bra DONE_%=;\n\t"
        "bra.uni WAIT_%=;\n\t"
        "DONE_%=:\n\t"
        "}"
        :: "r"(mbar), "r"(parity) : "memory");
}

extern __shared__ char dynsmem[];

__global__ void gemv_tma_kernel(
    const float* __restrict__ x,
    const float* __restrict__ y,
    const float* __restrict__ W,
    float* __restrict__ out)
{
    Smem* s = reinterpret_cast<Smem*>(dynsmem);

    const int tid  = threadIdx.x;
    const int warp = tid >> 5;
    const int lane = tid & 31;

    const uint32_t mbar_base = (uint32_t)__cvta_generic_to_shared(&s->mbar[0]);

    if (tid == 0) {
        #pragma unroll
        for (int d = 0; d < DEPTH; d++)
            mbar_init(mbar_base + d * 8, 1);
        // Make inits visible to the async proxy before first TMA use.
        asm volatile("fence.proxy.async.shared::cta;" ::: "memory");
    }
    __syncthreads();

    const char* wbase = reinterpret_cast<const char*>(
        W + (size_t)blockIdx.x * ROWS_PER_BLOCK * N);

    // Prologue: fill the ring — 4 x 32 KB in flight immediately.
    if (tid == 0) {
        #pragma unroll
        for (int d = 0; d < DEPTH; d++) {
            uint32_t mb = mbar_base + d * 8;
            mbar_expect_tx(mb, STAGE_BYTES);
            bulk_load((uint32_t)__cvta_generic_to_shared(&s->w[d][0]),
                      wbase + (size_t)d * STAGE_BYTES, STAGE_BYTES, mb);
        }
    }

    // Stage r = tanh(y) while the first TMA stages are in flight.
    {
        const float4* y4 = reinterpret_cast<const float4*>(y);
        float4* r4 = reinterpret_cast<float4*>(s->r);
        #pragma unroll
        for (int i = tid; i < N / 4; i += THREADS) {
            float4 v = y4[i];
            float4 t;
            t.x = fast_tanh(v.x); t.y = fast_tanh(v.y);
            t.z = fast_tanh(v.z); t.w = fast_tanh(v.w);
            r4[i] = t;
        }
    }
    __syncthreads();

    const float4* rr = reinterpret_cast<const float4*>(s->r);

    // 8 stages; stage = one row of this block's rowgroup.
    #pragma unroll
    for (int st = 0; st < ROWS_PER_BLOCK; st++) {
        const int buf    = st & (DEPTH - 1);
        const uint32_t parity = (st / DEPTH) & 1;
        mbar_wait(mbar_base + buf * 8, parity);

        const float4* wb = reinterpret_cast<const float4*>(&s->w[buf][0]);
        float p = 0.f;
        #pragma unroll
        for (int k = 0; k < 8; k++) {   // 2048 float4 / 256 threads = 8 each
            float4 a = wb[k * THREADS + tid];
            float4 b = rr[k * THREADS + tid];
            p += a.x * b.x + a.y * b.y + a.z * b.z + a.w * b.w;
        }
        #pragma unroll
        for (int off = 16; off > 0; off >>= 1)
            p += __shfl_xor_sync(0xFFFFFFFFu, p, off);
        if (lane == 0)
            s->warp_part[st][warp] = p;

        __syncthreads();   // everyone done with w[buf]; warp_part[st] visible

        // Refill this buffer with the stage DEPTH ahead.
        if (tid == 0 && st + DEPTH < ROWS_PER_BLOCK) {
            uint32_t mb = mbar_base + buf * 8;
            mbar_expect_tx(mb, STAGE_BYTES);
            bulk_load((uint32_t)__cvta_generic_to_shared(&s->w[buf][0]),
                      wbase + (size_t)(st + DEPTH) * STAGE_BYTES, STAGE_BYTES, mb);
        }
    }

    // Finalize: warp 0, lanes 0..7 -> one row each, fixed summation order.
    if (warp == 0 && lane < ROWS_PER_BLOCK) {
        float sum = 0.f;
        #pragma unroll
        for (int j = 0; j < 8; j++)
            sum += s->warp_part[lane][j];
        const int row = blockIdx.x * ROWS_PER_BLOCK + lane;
        const float DT  = 1e-3f;
        const float TAU = 1e-2f;
        float yr = y[row];
        out[row] = yr + DT * ((-yr + sum + x[row]) / TAU);
    }
}

extern "C" void kernel_launch(void* const* d_in, const int* in_sizes, int n_in,
                              void* d_out, int out_size)
{
    const float* x = (const float*)d_in[0];
    const float* y = (const float*)d_in[1];
    const float* W = (const float*)d_in[2];
    float* out = (float*)d_out;

    static int configured = 0;
    if (!configured) {
        cudaFuncSetAttribute(gemv_tma_kernel,
                             cudaFuncAttributeMaxDynamicSharedMemorySize,
                             (int)sizeof(Smem));
        configured = 1;
    }

    gemv_tma_kernel<<<GRID, THREADS, sizeof(Smem)>>>(x, y, W, out);
}